// round 9
// baseline (speedup 1.0000x reference)
#include <cuda_runtime.h>

// SimpleSNN: T=500 sequential steps, B=2048, 12 -> 38 (RLeaky) -> 7 (Leaky)
// Outputs flat: spk1[T,B,38], mem1[T,B,38], spk2[T,B,7], mem2[T,B,7]
//
// Round-batched pipeline, G=10 steps per __syncthreads (50 barriers total).
// L1 recurrence is thread-local -> 10 unsynced steps into a 20-slot spk1 ring;
// L2 consumes the previous round concurrently. x is staged one round ahead
// via cp.async (global->shared, no registers, no STS).
// Per-step arithmetic order is bit-identical to the passing round-3 kernel.

#define T_STEPS  500
#define BATCH    2048
#define NIN      12
#define NL1      38
#define NL2      7
#define NB       4              // batch elements per block
#define NTHREADS 192
#define L1_T     (NB*NL1)       // 152
#define L2_BASE  160            // L2 warp starts at warp boundary
#define L2_T     (NB*NL2)       // 28
#define X_T      (NB*NIN)       // 48
#define W2STRIDE 44             // padded W2 row stride
#define G        10             // steps per round
#define S1SLOT_F (NB*40)        // floats per s1 slot (rows padded to 40)

#define CPA4(dst, src)  asm volatile("cp.async.ca.shared.global [%0], [%1], 4;" \
                                     :: "r"(dst), "l"(src) : "memory")
#define CPCOMMIT()      asm volatile("cp.async.commit_group;" ::: "memory")
#define CPWAIT0()       asm volatile("cp.async.wait_group 0;" ::: "memory")

__global__ __launch_bounds__(NTHREADS, 4)
void snn_scan_kernel(const float* __restrict__ x,
                     const float* __restrict__ W1,
                     const float* __restrict__ V,
                     const float* __restrict__ W2,
                     const float* __restrict__ pb1,
                     const float* __restrict__ pb2,
                     const float* __restrict__ pth,
                     float* __restrict__ out)
{
    __shared__ float xsh[2 * G][X_T];        // x ring: two rounds of slots
    __shared__ float s1sh[2 * G][S1SLOT_F];  // spk1 ring: two rounds
    __shared__ float w2sh[NL2 * W2STRIDE];   // W2 rows, padded stride

    const int tid = threadIdx.x;
    const int b0  = blockIdx.x * NB;

    const float beta1 = *pb1;
    const float beta2 = *pb2;
    const float thr   = *pth;

    const size_t stepx = (size_t)BATCH * NIN;
    const size_t step1 = (size_t)BATCH * NL1;
    const size_t step2 = (size_t)BATCH * NL2;

    // ---- one-time shared init ----
    for (int i = tid; i < NL2 * W2STRIDE; i += NTHREADS) {
        int k = i / W2STRIDE;
        int j = i - k * W2STRIDE;
        w2sh[i] = (j < NL1) ? W2[k * NL1 + j] : 0.0f;
    }
    // zero the 2 padding lanes of each batch row in all 20 slots (160 writes)
    if (tid < 160) {
        int sl = tid >> 3, r = tid & 7;
        s1sh[sl][(r >> 1) * 40 + 38 + (r & 1)] = 0.0f;
    }

    const bool isL1 = (tid < L1_T);
    const bool isX  = (tid < X_T);
    const bool isL2 = (tid >= L2_BASE) && (tid < L2_BASE + L2_T);

    // ---- layer 1 per-thread state ----
    float w1r[NIN];
    float vj = 0.f, mem1 = 0.f, spk1 = 0.f;
    int xoff = 0, s1idx = 0;
    float *pS1 = out, *pM1 = out;
    if (isL1) {
        int bl = tid / NL1, j = tid - bl * NL1;
        #pragma unroll
        for (int i = 0; i < NIN; ++i) w1r[i] = W1[j * NIN + i];
        vj    = V[j];
        xoff  = bl * NIN;
        s1idx = bl * 40 + j;
        size_t o = (size_t)(b0 + bl) * NL1 + j;
        pS1 = out + o;
        pM1 = out + (size_t)T_STEPS * BATCH * NL1 + o;
    }

    // ---- layer 2 per-thread state (W2 in shared) ----
    float mem2 = 0.f;
    int s2off = 0;
    const float4* w2v = (const float4*)w2sh;
    float *pS2 = out, *pM2 = out;
    if (isL2) {
        int t2 = tid - L2_BASE;
        int bl = t2 / NL2, k = t2 - bl * NL2;
        s2off = bl * 40;
        w2v   = (const float4*)&w2sh[k * W2STRIDE];
        size_t o = (size_t)(b0 + bl) * NL2 + k;
        pS2 = out + (size_t)2 * T_STEPS * BATCH * NL1 + o;
        pM2 = pS2 + (size_t)T_STEPS * BATCH * NL2;
    }

    // ---- x staging: cp.async round 0 into half 0 ----
    const float* xp = x + (size_t)b0 * NIN + tid;   // valid for tid < 48
    const unsigned xsh_u32 =
        (unsigned)__cvta_generic_to_shared(&xsh[0][0]) + (unsigned)tid * 4u;
    int tpre = 0;   // next step-base to stage
    if (isX) {
        #pragma unroll
        for (int s = 0; s < G; ++s)
            CPA4(xsh_u32 + (unsigned)s * (X_T * 4), xp + (size_t)s * stepx);
        CPCOMMIT();
        xp += (size_t)G * stepx;
        CPWAIT0();
    }
    tpre = G;
    __syncthreads();

    // One L1 step. Arguments are evaluated into locals FIRST (before any other
    // macro-local declarations) so expansion can't capture macro locals.
    // Serial fmaf chain — EXACT order of the passing kernel.
#define L1STEP(XP, S1P)                                                        \
        {                                                                      \
            const float4* xv_  = (const float4*)(XP);                          \
            float*       s1p_  = (S1P);                                        \
            float4 a = xv_[0], b = xv_[1], c = xv_[2];                         \
            float cur = a.x * w1r[0];                                          \
            cur = fmaf(a.y, w1r[1], cur);                                      \
            cur = fmaf(a.z, w1r[2], cur);                                      \
            cur = fmaf(a.w, w1r[3], cur);                                      \
            cur = fmaf(b.x, w1r[4], cur);                                      \
            cur = fmaf(b.y, w1r[5], cur);                                      \
            cur = fmaf(b.z, w1r[6], cur);                                      \
            cur = fmaf(b.w, w1r[7], cur);                                      \
            cur = fmaf(c.x, w1r[8], cur);                                      \
            cur = fmaf(c.y, w1r[9], cur);                                      \
            cur = fmaf(c.z, w1r[10], cur);                                     \
            cur = fmaf(c.w, w1r[11], cur);                                     \
            float mv_ = fmaf(beta1, mem1, cur);                                \
            mv_ = fmaf(vj, spk1, mv_);                                         \
            float spv_ = (mv_ > thr) ? 1.0f : 0.0f;                            \
            mv_ = fmaf(-spv_, thr, mv_);                                       \
            mem1 = mv_; spk1 = spv_;                                           \
            *s1p_ = spv_;                                                      \
            *pS1 = spv_; *pM1 = mv_;                                           \
            pS1 += step1; pM1 += step1;                                        \
        }

    // One L2 step from s1 row at SP. Exact 4-acc accumulation order.
#define L2STEP(SP)                                                             \
        {                                                                      \
            const float4* sv_ = (const float4*)(SP);                           \
            float acc0 = 0.0f, acc1 = 0.0f, acc2 = 0.0f, acc3 = 0.0f;          \
            _Pragma("unroll")                                                  \
            for (int q = 0; q < 10; ++q) {                                     \
                float4 s4 = sv_[q];                                            \
                float4 w4 = w2v[q];                                            \
                acc0 = fmaf(s4.x, w4.x, acc0);                                 \
                acc1 = fmaf(s4.y, w4.y, acc1);                                 \
                acc2 = fmaf(s4.z, w4.z, acc2);                                 \
                acc3 = fmaf(s4.w, w4.w, acc3);                                 \
            }                                                                  \
            float cur2 = (acc0 + acc1) + (acc2 + acc3);                        \
            float m2_ = fmaf(beta2, mem2, cur2);                               \
            float s2_ = (m2_ > thr) ? 1.0f : 0.0f;                             \
            m2_ = fmaf(-s2_, thr, m2_);                                        \
            mem2 = m2_;                                                        \
            *pS2 = s2_; *pM2 = m2_;                                            \
            pS2 += step2; pM2 += step2;                                        \
        }

    // L1 round at ring half BASE (0 or G): stage next round's x into the
    // other half via cp.async, run G L1 steps, then drain the async group.
#define L1ROUND(BASE)                                                          \
        {                                                                      \
            if (isX && tpre < T_STEPS) {                                       \
                const unsigned d_ = xsh_u32 + (unsigned)((BASE) ^ G) * (X_T*4);\
                _Pragma("unroll")                                              \
                for (int cs = 0; cs < G; ++cs)                                 \
                    CPA4(d_ + (unsigned)cs * (X_T * 4), xp + (size_t)cs * stepx);\
                CPCOMMIT();                                                    \
                xp += (size_t)G * stepx;                                       \
            }                                                                  \
            tpre += G;                                                         \
            if (isL1) {                                                        \
                const float* xb_  = &xsh[BASE][0] + xoff;                      \
                float*       s1b_ = &s1sh[BASE][0] + s1idx;                    \
                _Pragma("unroll")                                              \
                for (int ls = 0; ls < G; ++ls)                                 \
                    L1STEP(xb_ + ls * X_T, s1b_ + ls * S1SLOT_F)               \
            }                                                                  \
            if (isX) CPWAIT0();                                                \
        }

#define L2ROUND(BASE)                                                          \
        if (isL2) {                                                            \
            const float* sb_ = &s1sh[BASE][0] + s2off;                         \
            _Pragma("unroll")                                                  \
            for (int ks = 0; ks < G; ++ks)                                     \
                L2STEP(sb_ + ks * S1SLOT_F)                                    \
        }

    // round 0: L1 only (stages round 1 into half G)
    L1ROUND(0)
    __syncthreads();

    // rounds 1..48 (24 pairs): L1 leads, L2 trails one round
    #pragma unroll 1
    for (int i = 0; i < 24; ++i) {
        L1ROUND(G) L2ROUND(0)
        __syncthreads();
        L1ROUND(0) L2ROUND(G)
        __syncthreads();
    }

    // round 49: L1 steps 490-499 (half G), L2 consumes round 48 (half 0)
    L1ROUND(G) L2ROUND(0)
    __syncthreads();

    // epilogue: L2 for steps 490-499 (half G)
    L2ROUND(G)

#undef L1STEP
#undef L2STEP
#undef L1ROUND
#undef L2ROUND
}

extern "C" void kernel_launch(void* const* d_in, const int* in_sizes, int n_in,
                              void* d_out, int out_size)
{
    const float* x   = (const float*)d_in[0];
    const float* W1  = (const float*)d_in[1];
    const float* V   = (const float*)d_in[2];
    const float* W2  = (const float*)d_in[3];
    const float* b1  = (const float*)d_in[4];
    const float* b2  = (const float*)d_in[5];
    const float* th  = (const float*)d_in[6];
    float* out = (float*)d_out;

    dim3 grid(BATCH / NB);   // 512 blocks; 4 blocks/SM -> single wave
    dim3 block(NTHREADS);
    snn_scan_kernel<<<grid, block>>>(x, W1, V, W2, b1, b2, th, out);
}

// round 10
// speedup vs baseline: 1.3544x; 1.3544x over previous
#include <cuda_runtime.h>

// SimpleSNN: T=500 sequential steps, B=2048, 12 -> 38 (RLeaky) -> 7 (Leaky)
// Outputs flat: spk1[T,B,38], mem1[T,B,38], spk2[T,B,7], mem2[T,B,7]
//
// Round-batched pipeline (G=4 steps per __syncthreads), register x prefetch
// (the round-7 167us champion), with ONE change: spk1 is published as a
// ballot BITMASK (1 VOTE + 1 per-warp STS instead of 152 STS; L2 reads 2
// words instead of 40 floats) and L2 uses predicated adds, which are
// bit-exact vs fmaf with 0/1 spikes.

#define T_STEPS  500
#define BATCH    2048
#define NIN      12
#define NL1      38
#define NL2      7
#define NB       4              // batch elements per block
#define NTHREADS 192
#define PROD_T   160            // warps 0-4 run the L1 step body (ballot needs full warps)
#define L1_T     (NB*NL1)       // 152 real L1 threads
#define L2_BASE  160            // L2 warp
#define L2_T     (NB*NL2)       // 28
#define X_T      (NB*NIN)       // 48
#define W2STRIDE 44             // padded W2 row stride (conflict-free broadcast)
#define GSTEP    4              // steps per round
#define NSLOT    8              // ring depth (2 rounds)

__global__ __launch_bounds__(NTHREADS, 4)
void snn_scan_kernel(const float* __restrict__ x,
                     const float* __restrict__ W1,
                     const float* __restrict__ V,
                     const float* __restrict__ W2,
                     const float* __restrict__ pb1,
                     const float* __restrict__ pb2,
                     const float* __restrict__ pth,
                     float* __restrict__ out)
{
    __shared__ float    xsh[NSLOT][X_T];   // x ring: one slot per step
    __shared__ unsigned sbit[NSLOT][8];    // spike bitmask ring: 5 words used/slot
    __shared__ float    w2sh[NL2 * W2STRIDE];

    const int tid  = threadIdx.x;
    const int wid  = tid >> 5;
    const int b0   = blockIdx.x * NB;
    const float thr = *pth;

    const size_t stepx = (size_t)BATCH * NIN;
    const size_t step1 = (size_t)BATCH * NL1;
    const size_t step2 = (size_t)BATCH * NL2;

    // ---- one-time shared init ----
    for (int i = tid; i < NL2 * W2STRIDE; i += NTHREADS) {
        int k = i / W2STRIDE;
        int j = i - k * W2STRIDE;
        w2sh[i] = (j < NL1) ? W2[k * NL1 + j] : 0.0f;
    }

    const bool isP  = (tid < PROD_T);   // runs L1 step body (incl. ballot)
    const bool isL1 = (tid < L1_T);     // real L1 neuron
    const bool isX  = (tid < X_T);
    const bool isL2 = (tid >= L2_BASE) && (tid < L2_BASE + L2_T);

    // ---- layer 1 per-thread state ----
    const float beta1 = *pb1;
    float w1r[NIN];
    float vj = 0.f, mem1 = 0.f, spk1 = 0.f;
    int xoff = 0;
    float *pS1 = out, *pM1 = out;
    if (isL1) {
        int bl = tid / NL1, j = tid - bl * NL1;
        #pragma unroll
        for (int i = 0; i < NIN; ++i) w1r[i] = W1[j * NIN + i];
        vj   = V[j];
        xoff = bl * NIN;
        size_t o = (size_t)(b0 + bl) * NL1 + j;
        pS1 = out + o;
        pM1 = out + (size_t)T_STEPS * BATCH * NL1 + o;
    } else {
        #pragma unroll
        for (int i = 0; i < NIN; ++i) w1r[i] = 0.f;  // lanes 152-159: defined math
    }

    // ---- layer 2 per-thread state ----
    const float beta2 = *pb2;
    float mem2 = 0.f;
    int w0i = 0, offi = 0;
    const float4* w2v = (const float4*)w2sh;
    float *pS2 = out, *pM2 = out;
    if (isL2) {
        int t2 = tid - L2_BASE;
        int bl = t2 / NL2, k = t2 - bl * NL2;
        int base = bl * NL1;               // bit index of (bl, j=0)
        w0i  = base >> 5;                  // 0,1,2,3 (off 0,6,12,18 -> 2 words)
        offi = base & 31;
        w2v  = (const float4*)&w2sh[k * W2STRIDE];
        size_t o = (size_t)(b0 + bl) * NL2 + k;
        pS2 = out + (size_t)2 * T_STEPS * BATCH * NL1 + o;
        pM2 = pS2 + (size_t)T_STEPS * BATCH * NL2;
    }

    // ---- x prefetch: slots 0-3 staged, steps 4-7 in regs (round-7 style) ----
    const float* xp = x + (size_t)b0 * NIN + tid;   // valid for tid < 48
    float xn0 = 0.f, xn1 = 0.f, xn2 = 0.f, xn3 = 0.f;
    int tpre = 2 * GSTEP;
    if (isX) {
        xsh[0][tid] = xp[0];
        xsh[1][tid] = xp[stepx];
        xsh[2][tid] = xp[2 * stepx];
        xsh[3][tid] = xp[3 * stepx];
        xn0 = xp[4 * stepx];
        xn1 = xp[5 * stepx];
        xn2 = xp[6 * stepx];
        xn3 = xp[7 * stepx];
        xp += 8 * stepx;
    }
    __syncthreads();

    // one L1 step from ring slot SLOT. Serial fmaf chain — EXACT passing order.
    // All 160 producer threads execute (ballot); stores gated by isL1.
#define L1STEP(SLOT)                                                           \
        {                                                                      \
            const float4* xv_ = (const float4*)&xsh[SLOT][xoff];               \
            float4 a = xv_[0], b = xv_[1], c = xv_[2];                         \
            float cur = a.x * w1r[0];                                          \
            cur = fmaf(a.y, w1r[1], cur);                                      \
            cur = fmaf(a.z, w1r[2], cur);                                      \
            cur = fmaf(a.w, w1r[3], cur);                                      \
            cur = fmaf(b.x, w1r[4], cur);                                      \
            cur = fmaf(b.y, w1r[5], cur);                                      \
            cur = fmaf(b.z, w1r[6], cur);                                      \
            cur = fmaf(b.w, w1r[7], cur);                                      \
            cur = fmaf(c.x, w1r[8], cur);                                      \
            cur = fmaf(c.y, w1r[9], cur);                                      \
            cur = fmaf(c.z, w1r[10], cur);                                     \
            cur = fmaf(c.w, w1r[11], cur);                                     \
            float mv_ = fmaf(beta1, mem1, cur);                                \
            mv_ = fmaf(vj, spk1, mv_);                                         \
            bool pr_ = (mv_ > thr);                                            \
            float spv_ = pr_ ? 1.0f : 0.0f;                                    \
            mv_ = fmaf(-spv_, thr, mv_);                                       \
            mem1 = mv_; spk1 = spv_;                                           \
            unsigned bb_ = __ballot_sync(0xFFFFFFFFu, isL1 && pr_);            \
            if ((tid & 31) == 0) sbit[SLOT][wid] = bb_;                        \
            if (isL1) {                                                        \
                *pS1 = spv_; *pM1 = mv_;                                       \
                pS1 += step1; pM1 += step1;                                    \
            }                                                                  \
        }

    // one L2 step from ring slot SLOT: 2-word bitmask read + predicated adds.
    // Bit-exact vs fmaf(spike, w, acc) since spike is 0/1; same acc pattern.
#define L2STEP(SLOT)                                                           \
        {                                                                      \
            unsigned lo_ = sbit[SLOT][w0i];                                    \
            unsigned hi_ = sbit[SLOT][w0i + 1];                                \
            unsigned long long vb_ =                                           \
                ((((unsigned long long)hi_) << 32) | lo_) >> offi;             \
            vb_ &= 0x3FFFFFFFFFull;   /* keep bits 0..37 (pad = 0) */          \
            float acc0 = 0.0f, acc1 = 0.0f, acc2 = 0.0f, acc3 = 0.0f;          \
            _Pragma("unroll")                                                  \
            for (int q = 0; q < 10; ++q) {                                     \
                float4 w4 = w2v[q];                                            \
                acc0 = ((vb_ >> (4 * q + 0)) & 1) ? acc0 + w4.x : acc0;        \
                acc1 = ((vb_ >> (4 * q + 1)) & 1) ? acc1 + w4.y : acc1;        \
                acc2 = ((vb_ >> (4 * q + 2)) & 1) ? acc2 + w4.z : acc2;        \
                acc3 = ((vb_ >> (4 * q + 3)) & 1) ? acc3 + w4.w : acc3;        \
            }                                                                  \
            float cur2 = (acc0 + acc1) + (acc2 + acc3);                        \
            float m2_ = fmaf(beta2, mem2, cur2);                               \
            float s2_ = (m2_ > thr) ? 1.0f : 0.0f;                             \
            m2_ = fmaf(-s2_, thr, m2_);                                        \
            mem2 = m2_;                                                        \
            *pS2 = s2_; *pM2 = m2_;                                            \
            pS2 += step2; pM2 += step2;                                        \
        }

#define L1ROUND(BASE)                                                          \
        if (isP) {                                                             \
            L1STEP(BASE + 0) L1STEP(BASE + 1) L1STEP(BASE + 2) L1STEP(BASE + 3)\
        }                                                                      \
        if (isX) {                                                             \
            xsh[(BASE ^ 4) + 0][tid] = xn0;                                    \
            xsh[(BASE ^ 4) + 1][tid] = xn1;                                    \
            xsh[(BASE ^ 4) + 2][tid] = xn2;                                    \
            xsh[(BASE ^ 4) + 3][tid] = xn3;                                    \
            if (tpre < T_STEPS) {                                              \
                xn0 = xp[0];                                                   \
                xn1 = xp[stepx];                                               \
                xn2 = xp[2 * stepx];                                           \
                xn3 = xp[3 * stepx];                                           \
                xp += 4 * stepx;                                               \
            }                                                                  \
            tpre += GSTEP;                                                     \
        }

#define L2ROUND(BASE)                                                          \
        if (isL2) {                                                            \
            L2STEP(BASE + 0) L2STEP(BASE + 1) L2STEP(BASE + 2) L2STEP(BASE + 3)\
        }

    // round 0: L1 only
    L1ROUND(0)
    __syncthreads();

    // rounds 1..124: L1 leads, L2 trails one round (62 pairs)
    #pragma unroll 1
    for (int r = 0; r < 62; ++r) {
        L1ROUND(4) L2ROUND(0)
        __syncthreads();
        L1ROUND(0) L2ROUND(4)
        __syncthreads();
    }

    // epilogue: L2 for steps 496-499 (slot base 0)
    L2ROUND(0)

#undef L1STEP
#undef L2STEP
#undef L1ROUND
#undef L2ROUND
}

extern "C" void kernel_launch(void* const* d_in, const int* in_sizes, int n_in,
                              void* d_out, int out_size)
{
    const float* x   = (const float*)d_in[0];
    const float* W1  = (const float*)d_in[1];
    const float* V   = (const float*)d_in[2];
    const float* W2  = (const float*)d_in[3];
    const float* b1  = (const float*)d_in[4];
    const float* b2  = (const float*)d_in[5];
    const float* th  = (const float*)d_in[6];
    float* out = (float*)d_out;

    dim3 grid(BATCH / NB);   // 512 blocks; 4 blocks/SM -> single wave
    dim3 block(NTHREADS);
    snn_scan_kernel<<<grid, block>>>(x, W1, V, W2, b1, b2, th, out);
}